// round 14
// baseline (speedup 1.0000x reference)
#include <cuda_runtime.h>
#include <cuda_fp16.h>
#include <math.h>
#include <cstdint>

#define DD 256      // D
#define EE 1024     // E
#define FF 1024     // F
#define NROWS 4096  // N
#define NCHUNK 23   // e-chunks: 32 d-tiles x 23 = 736 CTAs ~= one wave @5 CTA/SM
#define DT 8        // d-rows per CTA (measured-optimal 1:8 w:eW traffic ratio)
#define P4 (DD * FF / 4)

// ---- static scratch ----
__device__ float g_w[EE * EE];
__device__ __align__(16) __half g_part[(size_t)NCHUNK * DD * FF];  // 12 MB fp16 partials
__device__ float g_bpart[NCHUNK * FF];
__device__ float g_beff[FF];
__device__ __align__(16) __half g_xh[NROWS * DD];     // x fp16 [m][k]
__device__ __align__(16) __half g_wth[FF * DD];       // W_eff^T fp16 [n][k]

// ============================================================
// mma helpers
// ============================================================
__device__ __forceinline__ float f2tf32f(float x) {
    unsigned u;
    asm("cvt.rna.tf32.f32 %0, %1;" : "=r"(u) : "f"(x));
    return __uint_as_float(u);
}
__device__ __forceinline__ void mma_tf32(float* d, const unsigned* a, const unsigned* b) {
    asm volatile(
        "mma.sync.aligned.m16n8k8.row.col.f32.tf32.tf32.f32 "
        "{%0,%1,%2,%3}, {%4,%5,%6,%7}, {%8,%9}, {%0,%1,%2,%3};\n"
        : "+f"(d[0]), "+f"(d[1]), "+f"(d[2]), "+f"(d[3])
        : "r"(a[0]), "r"(a[1]), "r"(a[2]), "r"(a[3]), "r"(b[0]), "r"(b[1]));
}
__device__ __forceinline__ void mma_f16(float* d, const unsigned* a, const unsigned* b) {
    asm volatile(
        "mma.sync.aligned.m16n8k16.row.col.f32.f16.f16.f32 "
        "{%0,%1,%2,%3}, {%4,%5,%6,%7}, {%8,%9}, {%0,%1,%2,%3};\n"
        : "+f"(d[0]), "+f"(d[1]), "+f"(d[2]), "+f"(d[3])
        : "r"(a[0]), "r"(a[1]), "r"(a[2]), "r"(a[3]), "r"(b[0]), "r"(b[1]));
}

// ============================================================
// Kernel 1: gate GEMM (tf32, proven). C = g_w (device-bound).
// ============================================================
__global__ void __launch_bounds__(256, 2)
gate_tf32(const float* __restrict__ A, const float* __restrict__ B,
          const float* __restrict__ bias) {
    float* C = (float*)g_w;
    __shared__ __align__(16) float As[32][136];
    __shared__ __align__(16) float Bs[32][136];
    const int tid = threadIdx.x;
    const int wid = tid >> 5;
    const int lane = tid & 31;
    const int g = lane >> 2;
    const int tig = lane & 3;
    const int i0 = blockIdx.y * 128;
    const int j0 = blockIdx.x * 128;
    const int wm = (wid >> 1) * 32;
    const int wn = (wid & 1) * 64;

    float acc[2][8][4];
#pragma unroll
    for (int mt = 0; mt < 2; mt++)
#pragma unroll
        for (int nt = 0; nt < 8; nt++)
#pragma unroll
            for (int r = 0; r < 4; r++) acc[mt][nt][r] = 0.f;

    const int arow = tid >> 1;
    const int akc = (tid & 1) * 16;

    for (int k0 = 0; k0 < DD; k0 += 32) {
#pragma unroll
        for (int t = 0; t < 4; t++) {
            float4 v = *(const float4*)&A[(size_t)(i0 + arow) * DD + k0 + akc + t * 4];
            As[akc + t * 4 + 0][arow] = f2tf32f(v.x);
            As[akc + t * 4 + 1][arow] = f2tf32f(v.y);
            As[akc + t * 4 + 2][arow] = f2tf32f(v.z);
            As[akc + t * 4 + 3][arow] = f2tf32f(v.w);
        }
#pragma unroll
        for (int t = 0; t < 4; t++) {
            int f4id = tid + t * 256;
            int kk = f4id >> 5;
            int nc = (f4id & 31) * 4;
            float4 v = *(const float4*)&B[(size_t)(k0 + kk) * FF + j0 + nc];
            float4 w;
            w.x = f2tf32f(v.x); w.y = f2tf32f(v.y);
            w.z = f2tf32f(v.z); w.w = f2tf32f(v.w);
            *(float4*)&Bs[kk][nc] = w;
        }
        __syncthreads();
#pragma unroll
        for (int ks = 0; ks < 32; ks += 8) {
            unsigned af[2][4];
#pragma unroll
            for (int mt = 0; mt < 2; mt++) {
                int m0 = wm + mt * 16;
                af[mt][0] = __float_as_uint(As[ks + tig][m0 + g]);
                af[mt][1] = __float_as_uint(As[ks + tig][m0 + g + 8]);
                af[mt][2] = __float_as_uint(As[ks + tig + 4][m0 + g]);
                af[mt][3] = __float_as_uint(As[ks + tig + 4][m0 + g + 8]);
            }
            unsigned bf[8][2];
#pragma unroll
            for (int nt = 0; nt < 8; nt++) {
                int n0 = wn + nt * 8;
                bf[nt][0] = __float_as_uint(Bs[ks + tig][n0 + g]);
                bf[nt][1] = __float_as_uint(Bs[ks + tig + 4][n0 + g]);
            }
#pragma unroll
            for (int mt = 0; mt < 2; mt++)
#pragma unroll
                for (int nt = 0; nt < 8; nt++)
                    mma_tf32(acc[mt][nt], af[mt], bf[nt]);
        }
        __syncthreads();
    }
#pragma unroll
    for (int mt = 0; mt < 2; mt++) {
        int gi = i0 + wm + mt * 16 + g;
#pragma unroll
        for (int nt = 0; nt < 8; nt++) {
            int gj = j0 + wn + nt * 8 + tig * 2;
            float bx = bias[gj], by = bias[gj + 1];
            float2 v0, v1;
            v0.x = acc[mt][nt][0] + bx; v0.y = acc[mt][nt][1] + by;
            v1.x = acc[mt][nt][2] + bx; v1.y = acc[mt][nt][3] + by;
            *(float2*)&C[(size_t)gi * FF + gj] = v0;
            *(float2*)&C[(size_t)(gi + 8) * FF + gj] = v1;
        }
    }
}

// ============================================================
// Kernel 2: row softmax on g_w
// ============================================================
__global__ void softmax_rows() {
    const int row = blockIdx.x;
    const int tid = threadIdx.x;
    const int lane = tid & 31;
    const int wid = tid >> 5;
    float4* p = ((float4*)g_w) + (size_t)row * (EE / 4);
    float4 v = p[tid];
    __shared__ float red[8];
    __shared__ float bc;

    float m = fmaxf(fmaxf(v.x, v.y), fmaxf(v.z, v.w));
#pragma unroll
    for (int o = 16; o > 0; o >>= 1) m = fmaxf(m, __shfl_xor_sync(0xffffffffu, m, o));
    if (lane == 0) red[wid] = m;
    __syncthreads();
    if (tid == 0) {
        float t = red[0];
#pragma unroll
        for (int i = 1; i < 8; i++) t = fmaxf(t, red[i]);
        bc = t;
    }
    __syncthreads();
    m = bc;
    __syncthreads();
    v.x = expf(v.x - m); v.y = expf(v.y - m);
    v.z = expf(v.z - m); v.w = expf(v.w - m);
    float s = v.x + v.y + v.z + v.w;
#pragma unroll
    for (int o = 16; o > 0; o >>= 1) s += __shfl_xor_sync(0xffffffffu, s, o);
    if (lane == 0) red[wid] = s;
    __syncthreads();
    if (tid == 0) {
        float t = 0.f;
#pragma unroll
        for (int i = 0; i < 8; i++) t += red[i];
        bc = t;
    }
    __syncthreads();
    float inv = 1.f / bc;
    v.x *= inv; v.y *= inv; v.z *= inv; v.w *= inv;
    p[tid] = v;
}

// ============================================================
// Kernel 3: x -> fp16 (8 floats / thread)
// ============================================================
__global__ void cvt_x(const float* __restrict__ x) {
    const int idx = blockIdx.x * 256 + threadIdx.x;
    float4 v0 = ((const float4*)x)[idx * 2];
    float4 v1 = ((const float4*)x)[idx * 2 + 1];
    __half2 h[4];
    h[0] = __floats2half2_rn(v0.x, v0.y);
    h[1] = __floats2half2_rn(v0.z, v0.w);
    h[2] = __floats2half2_rn(v1.x, v1.y);
    h[3] = __floats2half2_rn(v1.z, v1.w);
    ((uint4*)g_xh)[idx] = *(uint4*)h;
}

// ============================================================
// Kernel 4: split-K W_eff partials (fp16 partial stores) + b_eff.
// grid (32 d-tiles, 23 e-chunks) = 736 CTAs ~= one wave @5 CTA/SM.
// DT=8 keeps 1:8 w:eW ratio; 5 CTAs/SM -> 40 warps latency coverage.
// ============================================================
__global__ void __launch_bounds__(256, 5)
weff_partial(const float* __restrict__ eW, const float* __restrict__ eb) {
    const int tid = threadIdx.x;
    const int d0 = blockIdx.x * DT;
    const int es = blockIdx.y;
    const int e0 = (es * EE) / NCHUNK;
    const int e1 = ((es + 1) * EE) / NCHUNK;
    const bool doB = (blockIdx.x == 0);

    float4 acc[DT];
#pragma unroll
    for (int i = 0; i < DT; i++) acc[i] = make_float4(0.f, 0.f, 0.f, 0.f);
    float4 bacc = make_float4(0.f, 0.f, 0.f, 0.f);

    const float4* wp = ((const float4*)g_w) + tid;
    const float4* ep = ((const float4*)eW) + (size_t)d0 * (FF / 4) + tid;
    const float4* bp = ((const float4*)eb) + tid;

    for (int e = e0; e < e1; e++) {
        float4 wv = wp[(size_t)e * (FF / 4)];
        if (doB) {
            float4 bv = __ldcs(bp + (size_t)e * (FF / 4));
            bacc.x += wv.x * bv.x; bacc.y += wv.y * bv.y;
            bacc.z += wv.z * bv.z; bacc.w += wv.w * bv.w;
        }
        const float4* ee = ep + (size_t)e * DD * (FF / 4);
#pragma unroll
        for (int dd = 0; dd < DT; dd++) {
            float4 ev = __ldcs(ee + (size_t)dd * (FF / 4));
            acc[dd].x += wv.x * ev.x;
            acc[dd].y += wv.y * ev.y;
            acc[dd].z += wv.z * ev.z;
            acc[dd].w += wv.w * ev.w;
        }
    }
    // fp16 partial store: 4 floats -> 2x half2 = uint2 (8 B)
    uint2* outp = ((uint2*)g_part) + ((size_t)es * DD + d0) * (FF / 4) + tid;
#pragma unroll
    for (int dd = 0; dd < DT; dd++) {
        __half2 lo = __floats2half2_rn(acc[dd].x, acc[dd].y);
        __half2 hi = __floats2half2_rn(acc[dd].z, acc[dd].w);
        uint2 pk;
        pk.x = *(unsigned*)&lo;
        pk.y = *(unsigned*)&hi;
        outp[(size_t)dd * (FF / 4)] = pk;
    }
    if (doB) ((float4*)g_bpart)[(size_t)es * (FF / 4) + tid] = bacc;
}

// ============================================================
// Kernel 5: deterministic reduce over 23 fp16 chunks (fp32 sums),
// 256 blocks (64d x 16f tiles), coalesced fp16 W_eff^T writes.
// ============================================================
__global__ void reduce_parts() {
    __shared__ __align__(16) __half sh_t[16][72];   // [f_local][d_local]
    const int t = threadIdx.x;
    const int bd = blockIdx.x & 3;      // 4 d-tiles of 64
    const int bf = blockIdx.x >> 2;     // 64 f-tiles of 16
    const int d0 = bd * 64;
    const int f0 = bf * 16;
    const int fi = t & 3;
    const int dl = t >> 2;

    const uint2* src = ((const uint2*)g_part)
                     + (size_t)(d0 + dl) * (FF / 4) + (f0 / 4 + fi);
    float4 s = make_float4(0.f, 0.f, 0.f, 0.f);
#pragma unroll
    for (int p = 0; p < NCHUNK; p++) {
        uint2 pk = src[(size_t)p * P4];
        float2 lo = __half22float2(*(const __half2*)&pk.x);
        float2 hi = __half22float2(*(const __half2*)&pk.y);
        s.x += lo.x; s.y += lo.y; s.z += hi.x; s.w += hi.y;
    }
    sh_t[fi * 4 + 0][dl] = __float2half_rn(s.x);
    sh_t[fi * 4 + 1][dl] = __float2half_rn(s.y);
    sh_t[fi * 4 + 2][dl] = __float2half_rn(s.z);
    sh_t[fi * 4 + 3][dl] = __float2half_rn(s.w);
    __syncthreads();

    if (t < 128) {
        int fl = t >> 3;
        int c = t & 7;
        *(uint4*)(g_wth + (size_t)(f0 + fl) * DD + d0 + c * 8) =
            *(const uint4*)&sh_t[fl][c * 8];
    }

    if (blockIdx.x == 0) {
        float4 b = make_float4(0.f, 0.f, 0.f, 0.f);
#pragma unroll
        for (int p = 0; p < NCHUNK; p++) {
            float4 v = ((const float4*)g_bpart)[(size_t)p * (FF / 4) + t];
            b.x += v.x; b.y += v.y; b.z += v.z; b.w += v.w;
        }
        ((float4*)g_beff)[t] = b;
    }
}

// ============================================================
// Kernel 6: final GEMM, fp16 HMMA m16n8k16, double-buffered. (proven)
// ============================================================
__global__ void __launch_bounds__(256, 2)
final_hmma(float* __restrict__ out) {
    __shared__ __align__(16) __half As[2][128][72];
    __shared__ __align__(16) __half Bs[2][128][72];
    const int tid = threadIdx.x;
    const int wid = tid >> 5;
    const int lane = tid & 31;
    const int g = lane >> 2;
    const int tig = lane & 3;
    const int i0 = blockIdx.y * 128;
    const int j0 = blockIdx.x * 128;
    const int wm = (wid >> 1) * 32;
    const int wn = (wid & 1) * 64;
    const int lr = tid >> 3;
    const int lc = (tid & 7) * 8;

    float acc[2][8][4];
#pragma unroll
    for (int mt = 0; mt < 2; mt++)
#pragma unroll
        for (int nt = 0; nt < 8; nt++)
#pragma unroll
            for (int r = 0; r < 4; r++) acc[mt][nt][r] = 0.f;

    auto load_stage = [&](int kc, int buf) {
#pragma unroll
        for (int t = 0; t < 4; t++) {
            int r = lr + t * 32;
            *(uint4*)&As[buf][r][lc] =
                *(const uint4*)(g_xh + (size_t)(i0 + r) * DD + kc * 64 + lc);
        }
#pragma unroll
        for (int t = 0; t < 4; t++) {
            int r = lr + t * 32;
            *(uint4*)&Bs[buf][r][lc] =
                *(const uint4*)(g_wth + (size_t)(j0 + r) * DD + kc * 64 + lc);
        }
    };

    load_stage(0, 0);
    __syncthreads();

#pragma unroll
    for (int kc = 0; kc < 4; kc++) {
        const int buf = kc & 1;
        if (kc < 3) load_stage(kc + 1, buf ^ 1);

#pragma unroll
        for (int ks = 0; ks < 64; ks += 16) {
            unsigned af[2][4];
#pragma unroll
            for (int mt = 0; mt < 2; mt++) {
                int m0 = wm + mt * 16;
                af[mt][0] = *(const unsigned*)&As[buf][m0 + g][ks + tig * 2];
                af[mt][1] = *(const unsigned*)&As[buf][m0 + g + 8][ks + tig * 2];
                af[mt][2] = *(const unsigned*)&As[buf][m0 + g][ks + tig * 2 + 8];
                af[mt][3] = *(const unsigned*)&As[buf][m0 + g + 8][ks + tig * 2 + 8];
            }
            unsigned bf[8][2];
#pragma unroll
            for (int nt = 0; nt < 8; nt++) {
                int n0 = wn + nt * 8;
                bf[nt][0] = *(const unsigned*)&Bs[buf][n0 + g][ks + tig * 2];
                bf[nt][1] = *(const unsigned*)&Bs[buf][n0 + g][ks + tig * 2 + 8];
            }
#pragma unroll
            for (int mt = 0; mt < 2; mt++)
#pragma unroll
                for (int nt = 0; nt < 8; nt++)
                    mma_f16(acc[mt][nt], af[mt], bf[nt]);
        }
        __syncthreads();
    }

#pragma unroll
    for (int mt = 0; mt < 2; mt++) {
        int gi = i0 + wm + mt * 16 + g;
#pragma unroll
        for (int nt = 0; nt < 8; nt++) {
            int gj = j0 + wn + nt * 8 + tig * 2;
            float bx = g_beff[gj], by = g_beff[gj + 1];
            float2 v0, v1;
            v0.x = acc[mt][nt][0] + bx; v0.y = acc[mt][nt][1] + by;
            v1.x = acc[mt][nt][2] + bx; v1.y = acc[mt][nt][3] + by;
            *(float2*)&out[(size_t)gi * FF + gj] = v0;
            *(float2*)&out[(size_t)(gi + 8) * FF + gj] = v1;
        }
    }
}

// ============================================================
extern "C" void kernel_launch(void* const* d_in, const int* in_sizes, int n_in,
                              void* d_out, int out_size) {
    const float* x  = (const float*)d_in[0];   // (4096, 256)
    const float* gW = (const float*)d_in[1];   // (256, 1024)
    const float* gb = (const float*)d_in[2];   // (1024,)
    const float* eW = (const float*)d_in[3];   // (1024, 256, 1024)
    const float* eb = (const float*)d_in[4];   // (1024, 1024)
    float* out = (float*)d_out;                // (4096, 1024)

    cvt_x<<<NROWS * DD / 8 / 256, 256>>>(x);
    gate_tf32<<<dim3(FF / 128, EE / 128), 256>>>(x, gW, gb);
    softmax_rows<<<EE, 256>>>();
    weff_partial<<<dim3(DD / DT, NCHUNK), 256>>>(eW, eb);
    reduce_parts<<<256, 256>>>();
    final_hmma<<<dim3(FF / 128, NROWS / 128), 256>>>(out);
}

// round 15
// speedup vs baseline: 1.2944x; 1.2944x over previous
#include <cuda_runtime.h>
#include <cuda_fp16.h>
#include <math.h>
#include <cstdint>

#define DD 256      // D
#define EE 1024     // E
#define FF 1024     // F
#define NROWS 4096  // N
#define NCHUNK 18   // e-chunks: 32 d-tiles x 18 = 576 CTAs = 1 wave @4 CTA/SM
#define DT 8        // d-rows per CTA (measured optimum, NO launch_bounds>4: spills!)
#define P4 (DD * FF / 4)

// ---- static scratch ----
__device__ float g_w[EE * EE];
__device__ __align__(16) __half g_part[(size_t)NCHUNK * DD * FF];  // 9.4 MB fp16 partials
__device__ float g_bpart[NCHUNK * FF];
__device__ float g_beff[FF];
__device__ __align__(16) __half g_xh[NROWS * DD];     // x fp16 [m][k]
__device__ __align__(16) __half g_wth[FF * DD];       // W_eff^T fp16 [n][k]

// ============================================================
// mma helpers
// ============================================================
__device__ __forceinline__ float f2tf32f(float x) {
    unsigned u;
    asm("cvt.rna.tf32.f32 %0, %1;" : "=r"(u) : "f"(x));
    return __uint_as_float(u);
}
__device__ __forceinline__ void mma_tf32(float* d, const unsigned* a, const unsigned* b) {
    asm volatile(
        "mma.sync.aligned.m16n8k8.row.col.f32.tf32.tf32.f32 "
        "{%0,%1,%2,%3}, {%4,%5,%6,%7}, {%8,%9}, {%0,%1,%2,%3};\n"
        : "+f"(d[0]), "+f"(d[1]), "+f"(d[2]), "+f"(d[3])
        : "r"(a[0]), "r"(a[1]), "r"(a[2]), "r"(a[3]), "r"(b[0]), "r"(b[1]));
}
__device__ __forceinline__ void mma_f16(float* d, const unsigned* a, const unsigned* b) {
    asm volatile(
        "mma.sync.aligned.m16n8k16.row.col.f32.f16.f16.f32 "
        "{%0,%1,%2,%3}, {%4,%5,%6,%7}, {%8,%9}, {%0,%1,%2,%3};\n"
        : "+f"(d[0]), "+f"(d[1]), "+f"(d[2]), "+f"(d[3])
        : "r"(a[0]), "r"(a[1]), "r"(a[2]), "r"(a[3]), "r"(b[0]), "r"(b[1]));
}

// ============================================================
// Kernel 1: gate GEMM (tf32, proven). C = g_w (device-bound).
// ============================================================
__global__ void __launch_bounds__(256, 2)
gate_tf32(const float* __restrict__ A, const float* __restrict__ B,
          const float* __restrict__ bias) {
    float* C = (float*)g_w;
    __shared__ __align__(16) float As[32][136];
    __shared__ __align__(16) float Bs[32][136];
    const int tid = threadIdx.x;
    const int wid = tid >> 5;
    const int lane = tid & 31;
    const int g = lane >> 2;
    const int tig = lane & 3;
    const int i0 = blockIdx.y * 128;
    const int j0 = blockIdx.x * 128;
    const int wm = (wid >> 1) * 32;
    const int wn = (wid & 1) * 64;

    float acc[2][8][4];
#pragma unroll
    for (int mt = 0; mt < 2; mt++)
#pragma unroll
        for (int nt = 0; nt < 8; nt++)
#pragma unroll
            for (int r = 0; r < 4; r++) acc[mt][nt][r] = 0.f;

    const int arow = tid >> 1;
    const int akc = (tid & 1) * 16;

    for (int k0 = 0; k0 < DD; k0 += 32) {
#pragma unroll
        for (int t = 0; t < 4; t++) {
            float4 v = *(const float4*)&A[(size_t)(i0 + arow) * DD + k0 + akc + t * 4];
            As[akc + t * 4 + 0][arow] = f2tf32f(v.x);
            As[akc + t * 4 + 1][arow] = f2tf32f(v.y);
            As[akc + t * 4 + 2][arow] = f2tf32f(v.z);
            As[akc + t * 4 + 3][arow] = f2tf32f(v.w);
        }
#pragma unroll
        for (int t = 0; t < 4; t++) {
            int f4id = tid + t * 256;
            int kk = f4id >> 5;
            int nc = (f4id & 31) * 4;
            float4 v = *(const float4*)&B[(size_t)(k0 + kk) * FF + j0 + nc];
            float4 w;
            w.x = f2tf32f(v.x); w.y = f2tf32f(v.y);
            w.z = f2tf32f(v.z); w.w = f2tf32f(v.w);
            *(float4*)&Bs[kk][nc] = w;
        }
        __syncthreads();
#pragma unroll
        for (int ks = 0; ks < 32; ks += 8) {
            unsigned af[2][4];
#pragma unroll
            for (int mt = 0; mt < 2; mt++) {
                int m0 = wm + mt * 16;
                af[mt][0] = __float_as_uint(As[ks + tig][m0 + g]);
                af[mt][1] = __float_as_uint(As[ks + tig][m0 + g + 8]);
                af[mt][2] = __float_as_uint(As[ks + tig + 4][m0 + g]);
                af[mt][3] = __float_as_uint(As[ks + tig + 4][m0 + g + 8]);
            }
            unsigned bf[8][2];
#pragma unroll
            for (int nt = 0; nt < 8; nt++) {
                int n0 = wn + nt * 8;
                bf[nt][0] = __float_as_uint(Bs[ks + tig][n0 + g]);
                bf[nt][1] = __float_as_uint(Bs[ks + tig + 4][n0 + g]);
            }
#pragma unroll
            for (int mt = 0; mt < 2; mt++)
#pragma unroll
                for (int nt = 0; nt < 8; nt++)
                    mma_tf32(acc[mt][nt], af[mt], bf[nt]);
        }
        __syncthreads();
    }
#pragma unroll
    for (int mt = 0; mt < 2; mt++) {
        int gi = i0 + wm + mt * 16 + g;
#pragma unroll
        for (int nt = 0; nt < 8; nt++) {
            int gj = j0 + wn + nt * 8 + tig * 2;
            float bx = bias[gj], by = bias[gj + 1];
            float2 v0, v1;
            v0.x = acc[mt][nt][0] + bx; v0.y = acc[mt][nt][1] + by;
            v1.x = acc[mt][nt][2] + bx; v1.y = acc[mt][nt][3] + by;
            *(float2*)&C[(size_t)gi * FF + gj] = v0;
            *(float2*)&C[(size_t)(gi + 8) * FF + gj] = v1;
        }
    }
}

// ============================================================
// Kernel 2: row softmax on g_w
// ============================================================
__global__ void softmax_rows() {
    const int row = blockIdx.x;
    const int tid = threadIdx.x;
    const int lane = tid & 31;
    const int wid = tid >> 5;
    float4* p = ((float4*)g_w) + (size_t)row * (EE / 4);
    float4 v = p[tid];
    __shared__ float red[8];
    __shared__ float bc;

    float m = fmaxf(fmaxf(v.x, v.y), fmaxf(v.z, v.w));
#pragma unroll
    for (int o = 16; o > 0; o >>= 1) m = fmaxf(m, __shfl_xor_sync(0xffffffffu, m, o));
    if (lane == 0) red[wid] = m;
    __syncthreads();
    if (tid == 0) {
        float t = red[0];
#pragma unroll
        for (int i = 1; i < 8; i++) t = fmaxf(t, red[i]);
        bc = t;
    }
    __syncthreads();
    m = bc;
    __syncthreads();
    v.x = expf(v.x - m); v.y = expf(v.y - m);
    v.z = expf(v.z - m); v.w = expf(v.w - m);
    float s = v.x + v.y + v.z + v.w;
#pragma unroll
    for (int o = 16; o > 0; o >>= 1) s += __shfl_xor_sync(0xffffffffu, s, o);
    if (lane == 0) red[wid] = s;
    __syncthreads();
    if (tid == 0) {
        float t = 0.f;
#pragma unroll
        for (int i = 0; i < 8; i++) t += red[i];
        bc = t;
    }
    __syncthreads();
    float inv = 1.f / bc;
    v.x *= inv; v.y *= inv; v.z *= inv; v.w *= inv;
    p[tid] = v;
}

// ============================================================
// Kernel 3: x -> fp16 (8 floats / thread)
// ============================================================
__global__ void cvt_x(const float* __restrict__ x) {
    const int idx = blockIdx.x * 256 + threadIdx.x;
    float4 v0 = ((const float4*)x)[idx * 2];
    float4 v1 = ((const float4*)x)[idx * 2 + 1];
    __half2 h[4];
    h[0] = __floats2half2_rn(v0.x, v0.y);
    h[1] = __floats2half2_rn(v0.z, v0.w);
    h[2] = __floats2half2_rn(v1.x, v1.y);
    h[3] = __floats2half2_rn(v1.z, v1.w);
    ((uint4*)g_xh)[idx] = *(uint4*)h;
}

// ============================================================
// Kernel 4: split-K W_eff partials (fp16 partial stores) + b_eff.
// grid (32 d-tiles, 18 e-chunks) = 576 CTAs = one wave @4 CTA/SM.
// NO bounds(256,5): forces regs=48 and spills acc to local (R14).
// ============================================================
__global__ void __launch_bounds__(256, 4)
weff_partial(const float* __restrict__ eW, const float* __restrict__ eb) {
    const int tid = threadIdx.x;
    const int d0 = blockIdx.x * DT;
    const int es = blockIdx.y;
    const int e0 = (es * EE) / NCHUNK;
    const int e1 = ((es + 1) * EE) / NCHUNK;
    const bool doB = (blockIdx.x == 0);

    float4 acc[DT];
#pragma unroll
    for (int i = 0; i < DT; i++) acc[i] = make_float4(0.f, 0.f, 0.f, 0.f);
    float4 bacc = make_float4(0.f, 0.f, 0.f, 0.f);

    const float4* wp = ((const float4*)g_w) + tid;
    const float4* ep = ((const float4*)eW) + (size_t)d0 * (FF / 4) + tid;
    const float4* bp = ((const float4*)eb) + tid;

    for (int e = e0; e < e1; e++) {
        float4 wv = wp[(size_t)e * (FF / 4)];
        if (doB) {
            float4 bv = __ldcs(bp + (size_t)e * (FF / 4));
            bacc.x += wv.x * bv.x; bacc.y += wv.y * bv.y;
            bacc.z += wv.z * bv.z; bacc.w += wv.w * bv.w;
        }
        const float4* ee = ep + (size_t)e * DD * (FF / 4);
#pragma unroll
        for (int dd = 0; dd < DT; dd++) {
            float4 ev = __ldcs(ee + (size_t)dd * (FF / 4));
            acc[dd].x += wv.x * ev.x;
            acc[dd].y += wv.y * ev.y;
            acc[dd].z += wv.z * ev.z;
            acc[dd].w += wv.w * ev.w;
        }
    }
    // fp16 partial store: 4 floats -> 2x half2 = uint2 (8 B)
    uint2* outp = ((uint2*)g_part) + ((size_t)es * DD + d0) * (FF / 4) + tid;
#pragma unroll
    for (int dd = 0; dd < DT; dd++) {
        __half2 lo = __floats2half2_rn(acc[dd].x, acc[dd].y);
        __half2 hi = __floats2half2_rn(acc[dd].z, acc[dd].w);
        uint2 pk;
        pk.x = *(unsigned*)&lo;
        pk.y = *(unsigned*)&hi;
        outp[(size_t)dd * (FF / 4)] = pk;
    }
    if (doB) ((float4*)g_bpart)[(size_t)es * (FF / 4) + tid] = bacc;
}

// ============================================================
// Kernel 5: deterministic reduce over 18 fp16 chunks (fp32 sums),
// 256 blocks (64d x 16f tiles), coalesced fp16 W_eff^T writes.
// ============================================================
__global__ void reduce_parts() {
    __shared__ __align__(16) __half sh_t[16][72];   // [f_local][d_local]
    const int t = threadIdx.x;
    const int bd = blockIdx.x & 3;      // 4 d-tiles of 64
    const int bf = blockIdx.x >> 2;     // 64 f-tiles of 16
    const int d0 = bd * 64;
    const int f0 = bf * 16;
    const int fi = t & 3;
    const int dl = t >> 2;

    const uint2* src = ((const uint2*)g_part)
                     + (size_t)(d0 + dl) * (FF / 4) + (f0 / 4 + fi);
    float4 s = make_float4(0.f, 0.f, 0.f, 0.f);
#pragma unroll
    for (int p = 0; p < NCHUNK; p++) {
        uint2 pk = src[(size_t)p * P4];
        float2 lo = __half22float2(*(const __half2*)&pk.x);
        float2 hi = __half22float2(*(const __half2*)&pk.y);
        s.x += lo.x; s.y += lo.y; s.z += hi.x; s.w += hi.y;
    }
    sh_t[fi * 4 + 0][dl] = __float2half_rn(s.x);
    sh_t[fi * 4 + 1][dl] = __float2half_rn(s.y);
    sh_t[fi * 4 + 2][dl] = __float2half_rn(s.z);
    sh_t[fi * 4 + 3][dl] = __float2half_rn(s.w);
    __syncthreads();

    if (t < 128) {
        int fl = t >> 3;
        int c = t & 7;
        *(uint4*)(g_wth + (size_t)(f0 + fl) * DD + d0 + c * 8) =
            *(const uint4*)&sh_t[fl][c * 8];
    }

    if (blockIdx.x == 0) {
        float4 b = make_float4(0.f, 0.f, 0.f, 0.f);
#pragma unroll
        for (int p = 0; p < NCHUNK; p++) {
            float4 v = ((const float4*)g_bpart)[(size_t)p * (FF / 4) + t];
            b.x += v.x; b.y += v.y; b.z += v.z; b.w += v.w;
        }
        ((float4*)g_beff)[t] = b;
    }
}

// ============================================================
// Kernel 6: final GEMM, fp16 HMMA m16n8k16, double-buffered. (proven)
// ============================================================
__global__ void __launch_bounds__(256, 2)
final_hmma(float* __restrict__ out) {
    __shared__ __align__(16) __half As[2][128][72];
    __shared__ __align__(16) __half Bs[2][128][72];
    const int tid = threadIdx.x;
    const int wid = tid >> 5;
    const int lane = tid & 31;
    const int g = lane >> 2;
    const int tig = lane & 3;
    const int i0 = blockIdx.y * 128;
    const int j0 = blockIdx.x * 128;
    const int wm = (wid >> 1) * 32;
    const int wn = (wid & 1) * 64;
    const int lr = tid >> 3;
    const int lc = (tid & 7) * 8;

    float acc[2][8][4];
#pragma unroll
    for (int mt = 0; mt < 2; mt++)
#pragma unroll
        for (int nt = 0; nt < 8; nt++)
#pragma unroll
            for (int r = 0; r < 4; r++) acc[mt][nt][r] = 0.f;

    auto load_stage = [&](int kc, int buf) {
#pragma unroll
        for (int t = 0; t < 4; t++) {
            int r = lr + t * 32;
            *(uint4*)&As[buf][r][lc] =
                *(const uint4*)(g_xh + (size_t)(i0 + r) * DD + kc * 64 + lc);
        }
#pragma unroll
        for (int t = 0; t < 4; t++) {
            int r = lr + t * 32;
            *(uint4*)&Bs[buf][r][lc] =
                *(const uint4*)(g_wth + (size_t)(j0 + r) * DD + kc * 64 + lc);
        }
    };

    load_stage(0, 0);
    __syncthreads();

#pragma unroll
    for (int kc = 0; kc < 4; kc++) {
        const int buf = kc & 1;
        if (kc < 3) load_stage(kc + 1, buf ^ 1);

#pragma unroll
        for (int ks = 0; ks < 64; ks += 16) {
            unsigned af[2][4];
#pragma unroll
            for (int mt = 0; mt < 2; mt++) {
                int m0 = wm + mt * 16;
                af[mt][0] = *(const unsigned*)&As[buf][m0 + g][ks + tig * 2];
                af[mt][1] = *(const unsigned*)&As[buf][m0 + g + 8][ks + tig * 2];
                af[mt][2] = *(const unsigned*)&As[buf][m0 + g][ks + tig * 2 + 8];
                af[mt][3] = *(const unsigned*)&As[buf][m0 + g + 8][ks + tig * 2 + 8];
            }
            unsigned bf[8][2];
#pragma unroll
            for (int nt = 0; nt < 8; nt++) {
                int n0 = wn + nt * 8;
                bf[nt][0] = *(const unsigned*)&Bs[buf][n0 + g][ks + tig * 2];
                bf[nt][1] = *(const unsigned*)&Bs[buf][n0 + g][ks + tig * 2 + 8];
            }
#pragma unroll
            for (int mt = 0; mt < 2; mt++)
#pragma unroll
                for (int nt = 0; nt < 8; nt++)
                    mma_f16(acc[mt][nt], af[mt], bf[nt]);
        }
        __syncthreads();
    }

#pragma unroll
    for (int mt = 0; mt < 2; mt++) {
        int gi = i0 + wm + mt * 16 + g;
#pragma unroll
        for (int nt = 0; nt < 8; nt++) {
            int gj = j0 + wn + nt * 8 + tig * 2;
            float bx = g_beff[gj], by = g_beff[gj + 1];
            float2 v0, v1;
            v0.x = acc[mt][nt][0] + bx; v0.y = acc[mt][nt][1] + by;
            v1.x = acc[mt][nt][2] + bx; v1.y = acc[mt][nt][3] + by;
            *(float2*)&out[(size_t)gi * FF + gj] = v0;
            *(float2*)&out[(size_t)(gi + 8) * FF + gj] = v1;
        }
    }
}

// ============================================================
extern "C" void kernel_launch(void* const* d_in, const int* in_sizes, int n_in,
                              void* d_out, int out_size) {
    const float* x  = (const float*)d_in[0];   // (4096, 256)
    const float* gW = (const float*)d_in[1];   // (256, 1024)
    const float* gb = (const float*)d_in[2];   // (1024,)
    const float* eW = (const float*)d_in[3];   // (1024, 256, 1024)
    const float* eb = (const float*)d_in[4];   // (1024, 1024)
    float* out = (float*)d_out;                // (4096, 1024)

    cvt_x<<<NROWS * DD / 8 / 256, 256>>>(x);
    gate_tf32<<<dim3(FF / 128, EE / 128), 256>>>(x, gW, gb);
    softmax_rows<<<EE, 256>>>();
    weff_partial<<<dim3(DD / DT, NCHUNK), 256>>>(eW, eb);
    reduce_parts<<<256, 256>>>();
    final_hmma<<<dim3(FF / 128, NROWS / 128), 256>>>(out);
}

// round 16
// speedup vs baseline: 1.3223x; 1.0216x over previous
#include <cuda_runtime.h>
#include <cuda_fp16.h>
#include <math.h>
#include <cstdint>

#define DD 256      // D
#define EE 1024     // E
#define FF 1024     // F
#define NROWS 4096  // N
#define NCHUNK 18   // e-chunks: 32 d-tiles x 18 = 576 CTAs = 1 wave @4 CTA/SM
#define DT 8        // d-rows per CTA (measured optimum; bounds(256,4) — 5 spills!)
#define P4 (DD * FF / 4)

// ---- static scratch ----
__device__ float g_w[EE * EE];
__device__ __align__(16) __half g_part[(size_t)NCHUNK * DD * FF];  // fp16 partials
__device__ float g_bpart[NCHUNK * FF];
__device__ float g_beff[FF];
__device__ __align__(16) __half g_xh[NROWS * DD];     // x fp16 [m][k]
__device__ __align__(16) __half g_wth[FF * DD];       // W_eff^T fp16 [n][k]

// ============================================================
// mma helpers
// ============================================================
__device__ __forceinline__ float f2tf32f(float x) {
    unsigned u;
    asm("cvt.rna.tf32.f32 %0, %1;" : "=r"(u) : "f"(x));
    return __uint_as_float(u);
}
__device__ __forceinline__ void mma_tf32(float* d, const unsigned* a, const unsigned* b) {
    asm volatile(
        "mma.sync.aligned.m16n8k8.row.col.f32.tf32.tf32.f32 "
        "{%0,%1,%2,%3}, {%4,%5,%6,%7}, {%8,%9}, {%0,%1,%2,%3};\n"
        : "+f"(d[0]), "+f"(d[1]), "+f"(d[2]), "+f"(d[3])
        : "r"(a[0]), "r"(a[1]), "r"(a[2]), "r"(a[3]), "r"(b[0]), "r"(b[1]));
}
__device__ __forceinline__ void mma_f16(float* d, const unsigned* a, const unsigned* b) {
    asm volatile(
        "mma.sync.aligned.m16n8k16.row.col.f32.f16.f16.f32 "
        "{%0,%1,%2,%3}, {%4,%5,%6,%7}, {%8,%9}, {%0,%1,%2,%3};\n"
        : "+f"(d[0]), "+f"(d[1]), "+f"(d[2]), "+f"(d[3])
        : "r"(a[0]), "r"(a[1]), "r"(a[2]), "r"(a[3]), "r"(b[0]), "r"(b[1]));
}

// ============================================================
// Kernel 1: gate GEMM (tf32) + x->fp16 cvt prologue.
// Tile 128x64 -> grid (16,8) = 128 CTAs (2x the old chip fill).
// 8 warps (4m x 2n), warp tile 32x32 (2 m16 x 4 n8), BK=32.
// ============================================================
__global__ void __launch_bounds__(256, 2)
gate_tf32(const float* __restrict__ A, const float* __restrict__ B,
          const float* __restrict__ bias) {
    float* C = (float*)g_w;
    __shared__ __align__(16) float As[32][136];
    __shared__ __align__(16) float Bs[32][72];
    const int tid = threadIdx.x;

    // ---- cvt prologue: x -> g_xh (grid-stride over 131072 uint4) ----
    {
        const int gid = (blockIdx.y * gridDim.x + blockIdx.x) * 256 + tid;
        const int nthreads = gridDim.x * gridDim.y * 256;   // 32768
        for (int idx = gid; idx < NROWS * DD / 8; idx += nthreads) {
            float4 v0 = ((const float4*)A)[idx * 2];
            float4 v1 = ((const float4*)A)[idx * 2 + 1];
            __half2 h[4];
            h[0] = __floats2half2_rn(v0.x, v0.y);
            h[1] = __floats2half2_rn(v0.z, v0.w);
            h[2] = __floats2half2_rn(v1.x, v1.y);
            h[3] = __floats2half2_rn(v1.z, v1.w);
            ((uint4*)g_xh)[idx] = *(uint4*)h;
        }
    }

    const int wid = tid >> 5;
    const int lane = tid & 31;
    const int g = lane >> 2;
    const int tig = lane & 3;
    const int i0 = blockIdx.y * 128;
    const int j0 = blockIdx.x * 64;
    const int wm = (wid >> 1) * 32;
    const int wn = (wid & 1) * 32;

    float acc[2][4][4];
#pragma unroll
    for (int mt = 0; mt < 2; mt++)
#pragma unroll
        for (int nt = 0; nt < 4; nt++)
#pragma unroll
            for (int r = 0; r < 4; r++) acc[mt][nt][r] = 0.f;

    const int arow = tid >> 1;
    const int akc = (tid & 1) * 16;

    for (int k0 = 0; k0 < DD; k0 += 32) {
        // A tile: 128 rows x 32 k -> As[k][m]
#pragma unroll
        for (int t = 0; t < 4; t++) {
            float4 v = *(const float4*)&A[(size_t)(i0 + arow) * DD + k0 + akc + t * 4];
            As[akc + t * 4 + 0][arow] = f2tf32f(v.x);
            As[akc + t * 4 + 1][arow] = f2tf32f(v.y);
            As[akc + t * 4 + 2][arow] = f2tf32f(v.z);
            As[akc + t * 4 + 3][arow] = f2tf32f(v.w);
        }
        // B tile: 32 k x 64 n -> Bs[k][n] (512 float4, 2/thread)
#pragma unroll
        for (int t = 0; t < 2; t++) {
            int f4id = tid + t * 256;
            int kk = f4id >> 4;
            int nc = (f4id & 15) * 4;
            float4 v = *(const float4*)&B[(size_t)(k0 + kk) * EE + j0 + nc];
            float4 w;
            w.x = f2tf32f(v.x); w.y = f2tf32f(v.y);
            w.z = f2tf32f(v.z); w.w = f2tf32f(v.w);
            *(float4*)&Bs[kk][nc] = w;
        }
        __syncthreads();
#pragma unroll
        for (int ks = 0; ks < 32; ks += 8) {
            unsigned af[2][4];
#pragma unroll
            for (int mt = 0; mt < 2; mt++) {
                int m0 = wm + mt * 16;
                af[mt][0] = __float_as_uint(As[ks + tig][m0 + g]);
                af[mt][1] = __float_as_uint(As[ks + tig][m0 + g + 8]);
                af[mt][2] = __float_as_uint(As[ks + tig + 4][m0 + g]);
                af[mt][3] = __float_as_uint(As[ks + tig + 4][m0 + g + 8]);
            }
            unsigned bf[4][2];
#pragma unroll
            for (int nt = 0; nt < 4; nt++) {
                int n0 = wn + nt * 8;
                bf[nt][0] = __float_as_uint(Bs[ks + tig][n0 + g]);
                bf[nt][1] = __float_as_uint(Bs[ks + tig + 4][n0 + g]);
            }
#pragma unroll
            for (int mt = 0; mt < 2; mt++)
#pragma unroll
                for (int nt = 0; nt < 4; nt++)
                    mma_tf32(acc[mt][nt], af[mt], bf[nt]);
        }
        __syncthreads();
    }
#pragma unroll
    for (int mt = 0; mt < 2; mt++) {
        int gi = i0 + wm + mt * 16 + g;
#pragma unroll
        for (int nt = 0; nt < 4; nt++) {
            int gj = j0 + wn + nt * 8 + tig * 2;
            float bx = bias[gj], by = bias[gj + 1];
            float2 v0, v1;
            v0.x = acc[mt][nt][0] + bx; v0.y = acc[mt][nt][1] + by;
            v1.x = acc[mt][nt][2] + bx; v1.y = acc[mt][nt][3] + by;
            *(float2*)&C[(size_t)gi * EE + gj] = v0;
            *(float2*)&C[(size_t)(gi + 8) * EE + gj] = v1;
        }
    }
}

// ============================================================
// Kernel 2: row softmax on g_w
// ============================================================
__global__ void softmax_rows() {
    const int row = blockIdx.x;
    const int tid = threadIdx.x;
    const int lane = tid & 31;
    const int wid = tid >> 5;
    float4* p = ((float4*)g_w) + (size_t)row * (EE / 4);
    float4 v = p[tid];
    __shared__ float red[8];
    __shared__ float bc;

    float m = fmaxf(fmaxf(v.x, v.y), fmaxf(v.z, v.w));
#pragma unroll
    for (int o = 16; o > 0; o >>= 1) m = fmaxf(m, __shfl_xor_sync(0xffffffffu, m, o));
    if (lane == 0) red[wid] = m;
    __syncthreads();
    if (tid == 0) {
        float t = red[0];
#pragma unroll
        for (int i = 1; i < 8; i++) t = fmaxf(t, red[i]);
        bc = t;
    }
    __syncthreads();
    m = bc;
    __syncthreads();
    v.x = expf(v.x - m); v.y = expf(v.y - m);
    v.z = expf(v.z - m); v.w = expf(v.w - m);
    float s = v.x + v.y + v.z + v.w;
#pragma unroll
    for (int o = 16; o > 0; o >>= 1) s += __shfl_xor_sync(0xffffffffu, s, o);
    if (lane == 0) red[wid] = s;
    __syncthreads();
    if (tid == 0) {
        float t = 0.f;
#pragma unroll
        for (int i = 0; i < 8; i++) t += red[i];
        bc = t;
    }
    __syncthreads();
    float inv = 1.f / bc;
    v.x *= inv; v.y *= inv; v.z *= inv; v.w *= inv;
    p[tid] = v;
}

// ============================================================
// Kernel 3: split-K W_eff partials (fp16 stores) + b_eff. (locked)
// ============================================================
__global__ void __launch_bounds__(256, 4)
weff_partial(const float* __restrict__ eW, const float* __restrict__ eb) {
    const int tid = threadIdx.x;
    const int d0 = blockIdx.x * DT;
    const int es = blockIdx.y;
    const int e0 = (es * EE) / NCHUNK;
    const int e1 = ((es + 1) * EE) / NCHUNK;
    const bool doB = (blockIdx.x == 0);

    float4 acc[DT];
#pragma unroll
    for (int i = 0; i < DT; i++) acc[i] = make_float4(0.f, 0.f, 0.f, 0.f);
    float4 bacc = make_float4(0.f, 0.f, 0.f, 0.f);

    const float4* wp = ((const float4*)g_w) + tid;
    const float4* ep = ((const float4*)eW) + (size_t)d0 * (FF / 4) + tid;
    const float4* bp = ((const float4*)eb) + tid;

    for (int e = e0; e < e1; e++) {
        float4 wv = wp[(size_t)e * (FF / 4)];
        if (doB) {
            float4 bv = __ldcs(bp + (size_t)e * (FF / 4));
            bacc.x += wv.x * bv.x; bacc.y += wv.y * bv.y;
            bacc.z += wv.z * bv.z; bacc.w += wv.w * bv.w;
        }
        const float4* ee = ep + (size_t)e * DD * (FF / 4);
#pragma unroll
        for (int dd = 0; dd < DT; dd++) {
            float4 ev = __ldcs(ee + (size_t)dd * (FF / 4));
            acc[dd].x += wv.x * ev.x;
            acc[dd].y += wv.y * ev.y;
            acc[dd].z += wv.z * ev.z;
            acc[dd].w += wv.w * ev.w;
        }
    }
    uint2* outp = ((uint2*)g_part) + ((size_t)es * DD + d0) * (FF / 4) + tid;
#pragma unroll
    for (int dd = 0; dd < DT; dd++) {
        __half2 lo = __floats2half2_rn(acc[dd].x, acc[dd].y);
        __half2 hi = __floats2half2_rn(acc[dd].z, acc[dd].w);
        uint2 pk;
        pk.x = *(unsigned*)&lo;
        pk.y = *(unsigned*)&hi;
        outp[(size_t)dd * (FF / 4)] = pk;
    }
    if (doB) ((float4*)g_bpart)[(size_t)es * (FF / 4) + tid] = bacc;
}

// ============================================================
// Kernel 4: deterministic reduce over 18 fp16 chunks (fp32 sums),
// 256 blocks (64d x 16f tiles), coalesced fp16 W_eff^T writes.
// ============================================================
__global__ void reduce_parts() {
    __shared__ __align__(16) __half sh_t[16][72];
    const int t = threadIdx.x;
    const int bd = blockIdx.x & 3;
    const int bf = blockIdx.x >> 2;
    const int d0 = bd * 64;
    const int f0 = bf * 16;
    const int fi = t & 3;
    const int dl = t >> 2;

    const uint2* src = ((const uint2*)g_part)
                     + (size_t)(d0 + dl) * (FF / 4) + (f0 / 4 + fi);
    float4 s = make_float4(0.f, 0.f, 0.f, 0.f);
#pragma unroll
    for (int p = 0; p < NCHUNK; p++) {
        uint2 pk = src[(size_t)p * P4];
        float2 lo = __half22float2(*(const __half2*)&pk.x);
        float2 hi = __half22float2(*(const __half2*)&pk.y);
        s.x += lo.x; s.y += lo.y; s.z += hi.x; s.w += hi.y;
    }
    sh_t[fi * 4 + 0][dl] = __float2half_rn(s.x);
    sh_t[fi * 4 + 1][dl] = __float2half_rn(s.y);
    sh_t[fi * 4 + 2][dl] = __float2half_rn(s.z);
    sh_t[fi * 4 + 3][dl] = __float2half_rn(s.w);
    __syncthreads();

    if (t < 128) {
        int fl = t >> 3;
        int c = t & 7;
        *(uint4*)(g_wth + (size_t)(f0 + fl) * DD + d0 + c * 8) =
            *(const uint4*)&sh_t[fl][c * 8];
    }

    if (blockIdx.x == 0) {
        float4 b = make_float4(0.f, 0.f, 0.f, 0.f);
#pragma unroll
        for (int p = 0; p < NCHUNK; p++) {
            float4 v = ((const float4*)g_bpart)[(size_t)p * (FF / 4) + t];
            b.x += v.x; b.y += v.y; b.z += v.z; b.w += v.w;
        }
        ((float4*)g_beff)[t] = b;
    }
}

// ============================================================
// Kernel 5: final GEMM, fp16 HMMA m16n8k16, double-buffered. (proven)
// ============================================================
__global__ void __launch_bounds__(256, 2)
final_hmma(float* __restrict__ out) {
    __shared__ __align__(16) __half As[2][128][72];
    __shared__ __align__(16) __half Bs[2][128][72];
    const int tid = threadIdx.x;
    const int wid = tid >> 5;
    const int lane = tid & 31;
    const int g = lane >> 2;
    const int tig = lane & 3;
    const int i0 = blockIdx.y * 128;
    const int j0 = blockIdx.x * 128;
    const int wm = (wid >> 1) * 32;
    const int wn = (wid & 1) * 64;
    const int lr = tid >> 3;
    const int lc = (tid & 7) * 8;

    float acc[2][8][4];
#pragma unroll
    for (int mt = 0; mt < 2; mt++)
#pragma unroll
        for (int nt = 0; nt < 8; nt++)
#pragma unroll
            for (int r = 0; r < 4; r++) acc[mt][nt][r] = 0.f;

    auto load_stage = [&](int kc, int buf) {
#pragma unroll
        for (int t = 0; t < 4; t++) {
            int r = lr + t * 32;
            *(uint4*)&As[buf][r][lc] =
                *(const uint4*)(g_xh + (size_t)(i0 + r) * DD + kc * 64 + lc);
        }
#pragma unroll
        for (int t = 0; t < 4; t++) {
            int r = lr + t * 32;
            *(uint4*)&Bs[buf][r][lc] =
                *(const uint4*)(g_wth + (size_t)(j0 + r) * DD + kc * 64 + lc);
        }
    };

    load_stage(0, 0);
    __syncthreads();

#pragma unroll
    for (int kc = 0; kc < 4; kc++) {
        const int buf = kc & 1;
        if (kc < 3) load_stage(kc + 1, buf ^ 1);

#pragma unroll
        for (int ks = 0; ks < 64; ks += 16) {
            unsigned af[2][4];
#pragma unroll
            for (int mt = 0; mt < 2; mt++) {
                int m0 = wm + mt * 16;
                af[mt][0] = *(const unsigned*)&As[buf][m0 + g][ks + tig * 2];
                af[mt][1] = *(const unsigned*)&As[buf][m0 + g + 8][ks + tig * 2];
                af[mt][2] = *(const unsigned*)&As[buf][m0 + g][ks + tig * 2 + 8];
                af[mt][3] = *(const unsigned*)&As[buf][m0 + g + 8][ks + tig * 2 + 8];
            }
            unsigned bf[8][2];
#pragma unroll
            for (int nt = 0; nt < 8; nt++) {
                int n0 = wn + nt * 8;
                bf[nt][0] = *(const unsigned*)&Bs[buf][n0 + g][ks + tig * 2];
                bf[nt][1] = *(const unsigned*)&Bs[buf][n0 + g][ks + tig * 2 + 8];
            }
#pragma unroll
            for (int mt = 0; mt < 2; mt++)
#pragma unroll
                for (int nt = 0; nt < 8; nt++)
                    mma_f16(acc[mt][nt], af[mt], bf[nt]);
        }
        __syncthreads();
    }

#pragma unroll
    for (int mt = 0; mt < 2; mt++) {
        int gi = i0 + wm + mt * 16 + g;
#pragma unroll
        for (int nt = 0; nt < 8; nt++) {
            int gj = j0 + wn + nt * 8 + tig * 2;
            float bx = g_beff[gj], by = g_beff[gj + 1];
            float2 v0, v1;
            v0.x = acc[mt][nt][0] + bx; v0.y = acc[mt][nt][1] + by;
            v1.x = acc[mt][nt][2] + bx; v1.y = acc[mt][nt][3] + by;
            *(float2*)&out[(size_t)gi * FF + gj] = v0;
            *(float2*)&out[(size_t)(gi + 8) * FF + gj] = v1;
        }
    }
}

// ============================================================
extern "C" void kernel_launch(void* const* d_in, const int* in_sizes, int n_in,
                              void* d_out, int out_size) {
    const float* x  = (const float*)d_in[0];   // (4096, 256)
    const float* gW = (const float*)d_in[1];   // (256, 1024)
    const float* gb = (const float*)d_in[2];   // (1024,)
    const float* eW = (const float*)d_in[3];   // (1024, 256, 1024)
    const float* eb = (const float*)d_in[4];   // (1024, 1024)
    float* out = (float*)d_out;                // (4096, 1024)

    gate_tf32<<<dim3(EE / 64, EE / 128), 256>>>(x, gW, gb);  // + cvt prologue
    softmax_rows<<<EE, 256>>>();
    weff_partial<<<dim3(DD / DT, NCHUNK), 256>>>(eW, eb);
    reduce_parts<<<256, 256>>>();
    final_hmma<<<dim3(FF / 128, NROWS / 128), 256>>>(out);
}

// round 17
// speedup vs baseline: 1.3225x; 1.0002x over previous
#include <cuda_runtime.h>
#include <cuda_fp16.h>
#include <math.h>
#include <cstdint>

#define DD 256      // D
#define EE 1024     // E
#define FF 1024     // F
#define NROWS 4096  // N
#define NCHUNK 18   // e-chunks: 32 d-tiles x 18 = 576 CTAs = 1 wave @4 CTA/SM
#define DT 8        // d-rows per CTA (measured optimum; bounds(256,4) — 5 spills!)
#define P4 (DD * FF / 4)

// ---- static scratch ----
__device__ float g_w[EE * EE];
__device__ __align__(16) __half g_part[(size_t)NCHUNK * DD * FF];  // fp16 partials
__device__ float g_bpart[NCHUNK * FF];
__device__ float g_beff[FF];
__device__ __align__(16) __half g_xh[NROWS * DD];     // x fp16 [m][k]
__device__ __align__(16) __half g_wth[FF * DD];       // W_eff^T fp16 [n][k]

// ============================================================
// mma helpers
// ============================================================
__device__ __forceinline__ float f2tf32f(float x) {
    unsigned u;
    asm("cvt.rna.tf32.f32 %0, %1;" : "=r"(u) : "f"(x));
    return __uint_as_float(u);
}
__device__ __forceinline__ void mma_tf32(float* d, const unsigned* a, const unsigned* b) {
    asm volatile(
        "mma.sync.aligned.m16n8k8.row.col.f32.tf32.tf32.f32 "
        "{%0,%1,%2,%3}, {%4,%5,%6,%7}, {%8,%9}, {%0,%1,%2,%3};\n"
        : "+f"(d[0]), "+f"(d[1]), "+f"(d[2]), "+f"(d[3])
        : "r"(a[0]), "r"(a[1]), "r"(a[2]), "r"(a[3]), "r"(b[0]), "r"(b[1]));
}
__device__ __forceinline__ void mma_f16(float* d, const unsigned* a, const unsigned* b) {
    asm volatile(
        "mma.sync.aligned.m16n8k16.row.col.f32.f16.f16.f32 "
        "{%0,%1,%2,%3}, {%4,%5,%6,%7}, {%8,%9}, {%0,%1,%2,%3};\n"
        : "+f"(d[0]), "+f"(d[1]), "+f"(d[2]), "+f"(d[3])
        : "r"(a[0]), "r"(a[1]), "r"(a[2]), "r"(a[3]), "r"(b[0]), "r"(b[1]));
}

// ============================================================
// Kernel 1: gate GEMM (tf32) + x->fp16 cvt prologue. (R16-proven)
// Tile 128x64 -> grid (16,8) = 128 CTAs.
// ============================================================
__global__ void __launch_bounds__(256, 2)
gate_tf32(const float* __restrict__ A, const float* __restrict__ B,
          const float* __restrict__ bias) {
    float* C = (float*)g_w;
    __shared__ __align__(16) float As[32][136];
    __shared__ __align__(16) float Bs[32][72];
    const int tid = threadIdx.x;

    // ---- cvt prologue: x -> g_xh (grid-stride over 131072 uint4) ----
    {
        const int gid = (blockIdx.y * gridDim.x + blockIdx.x) * 256 + tid;
        const int nthreads = gridDim.x * gridDim.y * 256;   // 32768
        for (int idx = gid; idx < NROWS * DD / 8; idx += nthreads) {
            float4 v0 = ((const float4*)A)[idx * 2];
            float4 v1 = ((const float4*)A)[idx * 2 + 1];
            __half2 h[4];
            h[0] = __floats2half2_rn(v0.x, v0.y);
            h[1] = __floats2half2_rn(v0.z, v0.w);
            h[2] = __floats2half2_rn(v1.x, v1.y);
            h[3] = __floats2half2_rn(v1.z, v1.w);
            ((uint4*)g_xh)[idx] = *(uint4*)h;
        }
    }

    const int wid = tid >> 5;
    const int lane = tid & 31;
    const int g = lane >> 2;
    const int tig = lane & 3;
    const int i0 = blockIdx.y * 128;
    const int j0 = blockIdx.x * 64;
    const int wm = (wid >> 1) * 32;
    const int wn = (wid & 1) * 32;

    float acc[2][4][4];
#pragma unroll
    for (int mt = 0; mt < 2; mt++)
#pragma unroll
        for (int nt = 0; nt < 4; nt++)
#pragma unroll
            for (int r = 0; r < 4; r++) acc[mt][nt][r] = 0.f;

    const int arow = tid >> 1;
    const int akc = (tid & 1) * 16;

    for (int k0 = 0; k0 < DD; k0 += 32) {
#pragma unroll
        for (int t = 0; t < 4; t++) {
            float4 v = *(const float4*)&A[(size_t)(i0 + arow) * DD + k0 + akc + t * 4];
            As[akc + t * 4 + 0][arow] = f2tf32f(v.x);
            As[akc + t * 4 + 1][arow] = f2tf32f(v.y);
            As[akc + t * 4 + 2][arow] = f2tf32f(v.z);
            As[akc + t * 4 + 3][arow] = f2tf32f(v.w);
        }
#pragma unroll
        for (int t = 0; t < 2; t++) {
            int f4id = tid + t * 256;
            int kk = f4id >> 4;
            int nc = (f4id & 15) * 4;
            float4 v = *(const float4*)&B[(size_t)(k0 + kk) * EE + j0 + nc];
            float4 w;
            w.x = f2tf32f(v.x); w.y = f2tf32f(v.y);
            w.z = f2tf32f(v.z); w.w = f2tf32f(v.w);
            *(float4*)&Bs[kk][nc] = w;
        }
        __syncthreads();
#pragma unroll
        for (int ks = 0; ks < 32; ks += 8) {
            unsigned af[2][4];
#pragma unroll
            for (int mt = 0; mt < 2; mt++) {
                int m0 = wm + mt * 16;
                af[mt][0] = __float_as_uint(As[ks + tig][m0 + g]);
                af[mt][1] = __float_as_uint(As[ks + tig][m0 + g + 8]);
                af[mt][2] = __float_as_uint(As[ks + tig + 4][m0 + g]);
                af[mt][3] = __float_as_uint(As[ks + tig + 4][m0 + g + 8]);
            }
            unsigned bf[4][2];
#pragma unroll
            for (int nt = 0; nt < 4; nt++) {
                int n0 = wn + nt * 8;
                bf[nt][0] = __float_as_uint(Bs[ks + tig][n0 + g]);
                bf[nt][1] = __float_as_uint(Bs[ks + tig + 4][n0 + g]);
            }
#pragma unroll
            for (int mt = 0; mt < 2; mt++)
#pragma unroll
                for (int nt = 0; nt < 4; nt++)
                    mma_tf32(acc[mt][nt], af[mt], bf[nt]);
        }
        __syncthreads();
    }
#pragma unroll
    for (int mt = 0; mt < 2; mt++) {
        int gi = i0 + wm + mt * 16 + g;
#pragma unroll
        for (int nt = 0; nt < 4; nt++) {
            int gj = j0 + wn + nt * 8 + tig * 2;
            float bx = bias[gj], by = bias[gj + 1];
            float2 v0, v1;
            v0.x = acc[mt][nt][0] + bx; v0.y = acc[mt][nt][1] + by;
            v1.x = acc[mt][nt][2] + bx; v1.y = acc[mt][nt][3] + by;
            *(float2*)&C[(size_t)gi * EE + gj] = v0;
            *(float2*)&C[(size_t)(gi + 8) * EE + gj] = v1;
        }
    }
}

// ============================================================
// Kernel 2: row softmax on g_w
// ============================================================
__global__ void softmax_rows() {
    const int row = blockIdx.x;
    const int tid = threadIdx.x;
    const int lane = tid & 31;
    const int wid = tid >> 5;
    float4* p = ((float4*)g_w) + (size_t)row * (EE / 4);
    float4 v = p[tid];
    __shared__ float red[8];
    __shared__ float bc;

    float m = fmaxf(fmaxf(v.x, v.y), fmaxf(v.z, v.w));
#pragma unroll
    for (int o = 16; o > 0; o >>= 1) m = fmaxf(m, __shfl_xor_sync(0xffffffffu, m, o));
    if (lane == 0) red[wid] = m;
    __syncthreads();
    if (tid == 0) {
        float t = red[0];
#pragma unroll
        for (int i = 1; i < 8; i++) t = fmaxf(t, red[i]);
        bc = t;
    }
    __syncthreads();
    m = bc;
    __syncthreads();
    v.x = expf(v.x - m); v.y = expf(v.y - m);
    v.z = expf(v.z - m); v.w = expf(v.w - m);
    float s = v.x + v.y + v.z + v.w;
#pragma unroll
    for (int o = 16; o > 0; o >>= 1) s += __shfl_xor_sync(0xffffffffu, s, o);
    if (lane == 0) red[wid] = s;
    __syncthreads();
    if (tid == 0) {
        float t = 0.f;
#pragma unroll
        for (int i = 0; i < 8; i++) t += red[i];
        bc = t;
    }
    __syncthreads();
    float inv = 1.f / bc;
    v.x *= inv; v.y *= inv; v.z *= inv; v.w *= inv;
    p[tid] = v;
}

// ============================================================
// Kernel 3: split-K W_eff partials (fp16 stores) + b_eff. (locked)
// ============================================================
__global__ void __launch_bounds__(256, 4)
weff_partial(const float* __restrict__ eW, const float* __restrict__ eb) {
    const int tid = threadIdx.x;
    const int d0 = blockIdx.x * DT;
    const int es = blockIdx.y;
    const int e0 = (es * EE) / NCHUNK;
    const int e1 = ((es + 1) * EE) / NCHUNK;
    const bool doB = (blockIdx.x == 0);

    float4 acc[DT];
#pragma unroll
    for (int i = 0; i < DT; i++) acc[i] = make_float4(0.f, 0.f, 0.f, 0.f);
    float4 bacc = make_float4(0.f, 0.f, 0.f, 0.f);

    const float4* wp = ((const float4*)g_w) + tid;
    const float4* ep = ((const float4*)eW) + (size_t)d0 * (FF / 4) + tid;
    const float4* bp = ((const float4*)eb) + tid;

    for (int e = e0; e < e1; e++) {
        float4 wv = wp[(size_t)e * (FF / 4)];
        if (doB) {
            float4 bv = __ldcs(bp + (size_t)e * (FF / 4));
            bacc.x += wv.x * bv.x; bacc.y += wv.y * bv.y;
            bacc.z += wv.z * bv.z; bacc.w += wv.w * bv.w;
        }
        const float4* ee = ep + (size_t)e * DD * (FF / 4);
#pragma unroll
        for (int dd = 0; dd < DT; dd++) {
            float4 ev = __ldcs(ee + (size_t)dd * (FF / 4));
            acc[dd].x += wv.x * ev.x;
            acc[dd].y += wv.y * ev.y;
            acc[dd].z += wv.z * ev.z;
            acc[dd].w += wv.w * ev.w;
        }
    }
    uint2* outp = ((uint2*)g_part) + ((size_t)es * DD + d0) * (FF / 4) + tid;
#pragma unroll
    for (int dd = 0; dd < DT; dd++) {
        __half2 lo = __floats2half2_rn(acc[dd].x, acc[dd].y);
        __half2 hi = __floats2half2_rn(acc[dd].z, acc[dd].w);
        uint2 pk;
        pk.x = *(unsigned*)&lo;
        pk.y = *(unsigned*)&hi;
        outp[(size_t)dd * (FF / 4)] = pk;
    }
    if (doB) ((float4*)g_bpart)[(size_t)es * (FF / 4) + tid] = bacc;
}

// ============================================================
// Kernel 4: deterministic reduce, 512 blocks (32d x 16f tiles),
// thread pairs (t, t+128) sum chunks [0,9) / [9,18) in fixed order,
// combine lo+hi via smem, transpose, coalesced fp16 writes.
// ============================================================
__global__ void reduce_parts() {
    __shared__ float4 sh[128];
    __shared__ __align__(16) __half sh_t[16][40];   // [f_local][d_local 0..31]
    const int t = threadIdx.x;
    const int lane128 = t & 127;
    const int half_ = t >> 7;
    const int bd = blockIdx.x & 7;      // 8 d-tiles of 32
    const int bf = blockIdx.x >> 3;     // 64 f-tiles of 16
    const int d0 = bd * 32;
    const int f0 = bf * 16;
    const int fi = lane128 & 3;         // float4 of f
    const int dl = lane128 >> 2;        // 0..31

    const uint2* src = ((const uint2*)g_part)
                     + (size_t)(half_ * 9) * P4
                     + (size_t)(d0 + dl) * (FF / 4) + (f0 / 4 + fi);
    float4 s = make_float4(0.f, 0.f, 0.f, 0.f);
#pragma unroll
    for (int p = 0; p < 9; p++) {
        uint2 pk = src[(size_t)p * P4];
        float2 lo = __half22float2(*(const __half2*)&pk.x);
        float2 hi = __half22float2(*(const __half2*)&pk.y);
        s.x += lo.x; s.y += lo.y; s.z += hi.x; s.w += hi.y;
    }
    if (half_) sh[lane128] = s;
    __syncthreads();
    if (!half_) {
        float4 h = sh[lane128];
        sh_t[fi * 4 + 0][dl] = __float2half_rn(s.x + h.x);
        sh_t[fi * 4 + 1][dl] = __float2half_rn(s.y + h.y);
        sh_t[fi * 4 + 2][dl] = __float2half_rn(s.z + h.z);
        sh_t[fi * 4 + 3][dl] = __float2half_rn(s.w + h.w);
    }
    __syncthreads();

    // write-out: 16 f rows x 32 halfs (4 uint4/row) = 64 uint4
    if (t < 64) {
        int fl = t >> 2;
        int c = t & 3;
        *(uint4*)(g_wth + (size_t)(f0 + fl) * DD + d0 + c * 8) =
            *(const uint4*)&sh_t[fl][c * 8];
    }

    if (blockIdx.x == 0) {
        float4 b = make_float4(0.f, 0.f, 0.f, 0.f);
#pragma unroll
        for (int p = 0; p < NCHUNK; p++) {
            float4 v = ((const float4*)g_bpart)[(size_t)p * (FF / 4) + t];
            b.x += v.x; b.y += v.y; b.z += v.z; b.w += v.w;
        }
        ((float4*)g_beff)[t] = b;
    }
}

// ============================================================
// Kernel 5: final GEMM, fp16 HMMA m16n8k16, double-buffered. (proven)
// ============================================================
__global__ void __launch_bounds__(256, 2)
final_hmma(float* __restrict__ out) {
    __shared__ __align__(16) __half As[2][128][72];
    __shared__ __align__(16) __half Bs[2][128][72];
    const int tid = threadIdx.x;
    const int wid = tid >> 5;
    const int lane = tid & 31;
    const int g = lane >> 2;
    const int tig = lane & 3;
    const int i0 = blockIdx.y * 128;
    const int j0 = blockIdx.x * 128;
    const int wm = (wid >> 1) * 32;
    const int wn = (wid & 1) * 64;
    const int lr = tid >> 3;
    const int lc = (tid & 7) * 8;

    float acc[2][8][4];
#pragma unroll
    for (int mt = 0; mt < 2; mt++)
#pragma unroll
        for (int nt = 0; nt < 8; nt++)
#pragma unroll
            for (int r = 0; r < 4; r++) acc[mt][nt][r] = 0.f;

    auto load_stage = [&](int kc, int buf) {
#pragma unroll
        for (int t = 0; t < 4; t++) {
            int r = lr + t * 32;
            *(uint4*)&As[buf][r][lc] =
                *(const uint4*)(g_xh + (size_t)(i0 + r) * DD + kc * 64 + lc);
        }
#pragma unroll
        for (int t = 0; t < 4; t++) {
            int r = lr + t * 32;
            *(uint4*)&Bs[buf][r][lc] =
                *(const uint4*)(g_wth + (size_t)(j0 + r) * DD + kc * 64 + lc);
        }
    };

    load_stage(0, 0);
    __syncthreads();

#pragma unroll
    for (int kc = 0; kc < 4; kc++) {
        const int buf = kc & 1;
        if (kc < 3) load_stage(kc + 1, buf ^ 1);

#pragma unroll
        for (int ks = 0; ks < 64; ks += 16) {
            unsigned af[2][4];
#pragma unroll
            for (int mt = 0; mt < 2; mt++) {
                int m0 = wm + mt * 16;
                af[mt][0] = *(const unsigned*)&As[buf][m0 + g][ks + tig * 2];
                af[mt][1] = *(const unsigned*)&As[buf][m0 + g + 8][ks + tig * 2];
                af[mt][2] = *(const unsigned*)&As[buf][m0 + g][ks + tig * 2 + 8];
                af[mt][3] = *(const unsigned*)&As[buf][m0 + g + 8][ks + tig * 2 + 8];
            }
            unsigned bf[8][2];
#pragma unroll
            for (int nt = 0; nt < 8; nt++) {
                int n0 = wn + nt * 8;
                bf[nt][0] = *(const unsigned*)&Bs[buf][n0 + g][ks + tig * 2];
                bf[nt][1] = *(const unsigned*)&Bs[buf][n0 + g][ks + tig * 2 + 8];
            }
#pragma unroll
            for (int mt = 0; mt < 2; mt++)
#pragma unroll
                for (int nt = 0; nt < 8; nt++)
                    mma_f16(acc[mt][nt], af[mt], bf[nt]);
        }
        __syncthreads();
    }

#pragma unroll
    for (int mt = 0; mt < 2; mt++) {
        int gi = i0 + wm + mt * 16 + g;
#pragma unroll
        for (int nt = 0; nt < 8; nt++) {
            int gj = j0 + wn + nt * 8 + tig * 2;
            float bx = g_beff[gj], by = g_beff[gj + 1];
            float2 v0, v1;
            v0.x = acc[mt][nt][0] + bx; v0.y = acc[mt][nt][1] + by;
            v1.x = acc[mt][nt][2] + bx; v1.y = acc[mt][nt][3] + by;
            *(float2*)&out[(size_t)gi * FF + gj] = v0;
            *(float2*)&out[(size_t)(gi + 8) * FF + gj] = v1;
        }
    }
}

// ============================================================
extern "C" void kernel_launch(void* const* d_in, const int* in_sizes, int n_in,
                              void* d_out, int out_size) {
    const float* x  = (const float*)d_in[0];   // (4096, 256)
    const float* gW = (const float*)d_in[1];   // (256, 1024)
    const float* gb = (const float*)d_in[2];   // (1024,)
    const float* eW = (const float*)d_in[3];   // (1024, 256, 1024)
    const float* eb = (const float*)d_in[4];   // (1024, 1024)
    float* out = (float*)d_out;                // (4096, 1024)

    gate_tf32<<<dim3(EE / 64, EE / 128), 256>>>(x, gW, gb);  // + cvt prologue
    softmax_rows<<<EE, 256>>>();
    weff_partial<<<dim3(DD / DT, NCHUNK), 256>>>(eW, eb);
    reduce_parts<<<512, 256>>>();
    final_hmma<<<dim3(FF / 128, NROWS / 128), 256>>>(out);
}